// round 14
// baseline (speedup 1.0000x reference)
#include <cuda_runtime.h>
#include <cuda_bf16.h>
#include <cuda_fp16.h>
#include <cuda_fp8.h>
#include <cstdint>
#include <math.h>

#define N_ROWS 16384
#define F_DIM  128
#define H1_DIM 64
#define H2_DIM 32
#define OUT_DIM 2

#define TB      128                       // gram tile (square), K=64 head
#define NB      (N_ROWS / TB)             // 128
#define N_TILES (NB * (NB + 1) / 2)       // 8256

#define SCREEN_T 0.9186f                  // sqrt(0.9) - 0.03 margin (fp8 dot + f16 acc noise)
#define TILE_BYTES 8192                   // 128 rows x 64B head
#define MLP_BLOCKS 256                    // 64 rows/block, 2 threads/row

// ---------------- device scratch (zero-initialized at load) ----------------
__device__ __align__(128) uint32_t g_x8[N_ROWS * 16];  // 1 MB: head rows pre-swizzled per 8KB tile
__device__ __align__(128) float    g_tail[N_ROWS];     // tail norm of normalized row
__device__ float    g_rnorm[N_ROWS];
__device__ float    g_neigh[N_ROWS * F_DIM];           // zero except edge rows (re-zeroed in k_mlp)
__device__ int      g_deg[N_ROWS];
__device__ double   g_sum[2];
__device__ double   g_sq[2];
__device__ int      g_done;

__device__ __forceinline__ uint32_t smem_u32(const void* p) {
    uint32_t a;
    asm("{ .reg .u64 t; cvta.to.shared.u64 t, %1; cvt.u32.u64 %0, t; }" : "=r"(a) : "l"(p));
    return a;
}

// byte offset inside an 8KB tile: two 64B logical rows per 128B smem row, XOR swizzle.
__device__ __forceinline__ uint32_t pack_off(int r, int c) {
    int R = r >> 1;
    int u = ((r & 1) << 2) | c;
    return (uint32_t)(R * 128 + ((u ^ (R & 7)) << 4));
}

// triangular decode: linear tile t -> (ib, jb), jb >= ib
__device__ __forceinline__ void decode_tile(int t, int& ib, int& jb) {
    int u = N_TILES - 1 - t;
    int rb = (int)((sqrtf(8.0f * (float)u + 1.0f) - 1.0f) * 0.5f);
    while (rb * (rb + 1) / 2 > u) rb--;
    while ((rb + 1) * (rb + 2) / 2 <= u) rb++;
    ib = NB - 1 - rb;
    jb = NB - 1 - (u - rb * (rb + 1) / 2);
}

__device__ __forceinline__ void bulk_cp(uint32_t dst, const void* src, uint32_t bytes,
                                        uint32_t mbar) {
    asm volatile(
        "cp.async.bulk.shared::cta.global.mbarrier::complete_tx::bytes [%0], [%1], %2, [%3];"
        :: "r"(dst), "l"(src), "r"(bytes), "r"(mbar) : "memory");
}
__device__ __forceinline__ void mbar_init(uint32_t addr, uint32_t cnt) {
    asm volatile("mbarrier.init.shared.b64 [%0], %1;" :: "r"(addr), "r"(cnt) : "memory");
}
__device__ __forceinline__ void mbar_expect_tx(uint32_t addr, uint32_t tx) {
    asm volatile("mbarrier.arrive.expect_tx.shared.b64 _, [%0], %1;"
                 :: "r"(addr), "r"(tx) : "memory");
}
__device__ __forceinline__ void mbar_wait(uint32_t addr, uint32_t parity) {
    asm volatile(
        "{\n\t.reg .pred P;\n\t"
        "WAITLP_%=:\n\t"
        "mbarrier.try_wait.parity.acquire.cta.shared::cta.b64 P, [%0], %1, 0x989680;\n\t"
        "@P bra.uni WAITDN_%=;\n\t"
        "bra.uni WAITLP_%=;\n\t"
        "WAITDN_%=:\n\t}"
        :: "r"(addr), "r"(parity) : "memory");
}

// packed f32x2 helpers
#define PACK2(out, lo, hi) \
    asm("mov.b64 %0, {%1, %2};" : "=l"(out) : "f"(lo), "f"(hi))
#define UNPACK2(lo, hi, in) \
    asm("mov.b64 {%0, %1}, %2;" : "=f"(lo), "=f"(hi) : "l"(in))
#define FMA2(acc, a, b) \
    asm("fma.rn.f32x2 %0, %1, %2, %0;" : "+l"(acc) : "l"(a), "l"(b))

// ---------------- kernel 1: norms, head->e4m3 (pre-swizzled), tail norms ----------------
// 8 lanes per row, 4 rows per warp: MLP=4 loads, 3-step butterfly reduce.
__global__ void __launch_bounds__(256) k_norm(const float* __restrict__ x) {
    if (blockIdx.x == 0 && threadIdx.x == 0) {
        g_sum[0] = 0.0; g_sum[1] = 0.0; g_sq[0] = 0.0; g_sq[1] = 0.0;
        g_done = 0;
    }
    int warp = (blockIdx.x * blockDim.x + threadIdx.x) >> 5;
    int lane = threadIdx.x & 31;
    int l = lane & 7;                 // lane within row (0..7)
    int row = warp * 4 + (lane >> 3); // 4 rows per warp
    if (row >= N_ROWS) return;

    const float4* xr = reinterpret_cast<const float4*>(x) + (size_t)row * 32;
    float4 v[4];
#pragma unroll
    for (int k = 0; k < 4; k++) v[k] = xr[l + 8 * k];   // k=0,1 head; k=2,3 tail

    float sh = v[0].x * v[0].x + v[0].y * v[0].y + v[0].z * v[0].z + v[0].w * v[0].w
             + v[1].x * v[1].x + v[1].y * v[1].y + v[1].z * v[1].z + v[1].w * v[1].w;
    float st = v[2].x * v[2].x + v[2].y * v[2].y + v[2].z * v[2].z + v[2].w * v[2].w
             + v[3].x * v[3].x + v[3].y * v[3].y + v[3].z * v[3].z + v[3].w * v[3].w;
#pragma unroll
    for (int o = 4; o > 0; o >>= 1) {
        sh += __shfl_xor_sync(0xffffffffu, sh, o);
        st += __shfl_xor_sync(0xffffffffu, st, o);
    }
    float ss = sh + st;
    float inv = 1.0f / (sqrtf(ss) + 1e-12f);

    int t = row >> 7, rl = row & 127;
#pragma unroll
    for (int h = 0; h < 2; h++) {     // head words: j = l and l+8
        __nv_fp8x2_storage_t p0 = __nv_cvt_float2_to_fp8x2(
            make_float2(v[h].x * inv, v[h].y * inv), __NV_SATFINITE, __NV_E4M3);
        __nv_fp8x2_storage_t p1 = __nv_cvt_float2_to_fp8x2(
            make_float2(v[h].z * inv, v[h].w * inv), __NV_SATFINITE, __NV_E4M3);
        uint32_t word = (uint32_t)p0 | ((uint32_t)p1 << 16);
        int j = l + 8 * h;
        g_x8[t * 2048 + (pack_off(rl, j >> 2) >> 2) + (j & 3)] = word;
    }
    if (l == 0) {
        g_tail[row] = sqrtf(st) * inv;
        g_rnorm[row] = inv;
        g_deg[row] = 0;
    }
}

// ---------------- kernel 2: fp8 head-gram (f16 acc, occ=3) + cheap screen + exact recheck ----------------
__global__ void __launch_bounds__(256, 3) k_gram(const float* __restrict__ x) {
    int ib, jb;
    decode_tile(blockIdx.x, ib, jb);
    bool diag = (ib == jb);

    __shared__ alignas(1024) char sA[TILE_BYTES];
    __shared__ alignas(1024) char sB[TILE_BYTES];
    __shared__ alignas(16) float stA[TB];
    __shared__ alignas(16) float stB[TB];
    __shared__ alignas(8) unsigned long long mbar_s;

    int tid = threadIdx.x;
    uint32_t sa = smem_u32(sA), sbm = smem_u32(sB);
    uint32_t mbar = smem_u32(&mbar_s);

    if (tid == 0) mbar_init(mbar, 1);
    __syncthreads();
    if (tid == 0) {
        uint32_t tx = diag ? (TILE_BYTES + 512) : (2 * TILE_BYTES + 1024);
        mbar_expect_tx(mbar, tx);
        bulk_cp(sa, g_x8 + (size_t)ib * 2048, TILE_BYTES, mbar);
        bulk_cp(smem_u32(stA), g_tail + ib * TB, 512, mbar);
        if (!diag) {
            bulk_cp(sbm, g_x8 + (size_t)jb * 2048, TILE_BYTES, mbar);
            bulk_cp(smem_u32(stB), g_tail + jb * TB, 512, mbar);
        }
    }
    mbar_wait(mbar, 0);

    uint32_t sb_use = diag ? sa : sbm;

    int wid = tid >> 5, lane = tid & 31;
    int m0 = (wid & 3) * 32;   // 4 warps along M
    int n0 = (wid >> 2) * 64;  // 2 warps along N

    // f16 accumulators
    uint32_t acc[2][8][2];
#pragma unroll
    for (int mi = 0; mi < 2; mi++)
#pragma unroll
        for (int nj = 0; nj < 8; nj++) {
            acc[mi][nj][0] = 0u; acc[mi][nj][1] = 0u;
        }

    int q = lane >> 3, L = lane & 7;
    int rq = (q & 1) * 8 + L;
    int kq = q >> 1;

#pragma unroll
    for (int kk = 0; kk < 2; kk++) {           // 2 chunks of k=32 fp8 (head only)
        int cbase = kk * 2 + kq;
        uint32_t a[2][4];
#pragma unroll
        for (int mi = 0; mi < 2; mi++) {
            uint32_t addr = sa + pack_off(m0 + mi * 16 + rq, cbase);
            asm volatile("ldmatrix.sync.aligned.m8n8.x4.shared.b16 {%0,%1,%2,%3}, [%4];"
                         : "=r"(a[mi][0]), "=r"(a[mi][1]), "=r"(a[mi][2]), "=r"(a[mi][3])
                         : "r"(addr));
        }
        uint32_t b[8][2];
#pragma unroll
        for (int nq4 = 0; nq4 < 4; nq4++) {
            uint32_t r0, r1, r2, r3;
            uint32_t addr = sb_use + pack_off(n0 + nq4 * 16 + rq, cbase);
            asm volatile("ldmatrix.sync.aligned.m8n8.x4.shared.b16 {%0,%1,%2,%3}, [%4];"
                         : "=r"(r0), "=r"(r1), "=r"(r2), "=r"(r3)
                         : "r"(addr));
            b[nq4 * 2 + 0][0] = r0; b[nq4 * 2 + 0][1] = r2;
            b[nq4 * 2 + 1][0] = r1; b[nq4 * 2 + 1][1] = r3;
        }
#pragma unroll
        for (int mi = 0; mi < 2; mi++)
#pragma unroll
            for (int nj = 0; nj < 8; nj++)
                asm volatile(
                    "mma.sync.aligned.m16n8k32.row.col.f16.e4m3.e4m3.f16 "
                    "{%0,%1}, {%2,%3,%4,%5}, {%6,%7}, {%0,%1};"
                    : "+r"(acc[mi][nj][0]), "+r"(acc[mi][nj][1])
                    : "r"(a[mi][0]), "r"(a[mi][1]), "r"(a[mi][2]), "r"(a[mi][3]),
                      "r"(b[nj][0]), "r"(b[nj][1]));
    }

    // ---- epilogue: minimal coarse screen (amax + warp-max tail bound) ----
    int g = lane >> 2, tg = lane & 3;
    const float* stB_use = diag ? stA : stB;

    __half2 hmax = __float2half2_rn(0.f);
#pragma unroll
    for (int mi = 0; mi < 2; mi++)
#pragma unroll
        for (int nj = 0; nj < 8; nj++)
#pragma unroll
            for (int r2 = 0; r2 < 2; r2++)
                hmax = __hmax2(hmax, __habs2(*reinterpret_cast<__half2*>(&acc[mi][nj][r2])));
    float amax = fmaxf(__low2float(hmax), __high2float(hmax));

    float timax = fmaxf(fmaxf(stA[m0 + g], stA[m0 + g + 8]),
                        fmaxf(stA[m0 + 16 + g], stA[m0 + 16 + g + 8]));
    float tjmax = fmaxf(stB_use[n0 + lane], stB_use[n0 + 32 + lane]);
#pragma unroll
    for (int o = 16; o > 0; o >>= 1)
        tjmax = fmaxf(tjmax, __shfl_xor_sync(0xffffffffu, tjmax, o));

    if (__any_sync(0xffffffffu, amax + timax * tjmax >= SCREEN_T)) {
        float ti[2][2];
#pragma unroll
        for (int mi = 0; mi < 2; mi++)
#pragma unroll
            for (int h = 0; h < 2; h++)
                ti[mi][h] = stA[m0 + mi * 16 + g + h * 8];
        float tj0[8], tj1[8];
#pragma unroll
        for (int nj = 0; nj < 8; nj++) {
            int j = n0 + nj * 8 + 2 * tg;
            tj0[nj] = stB_use[j];
            tj1[nj] = stB_use[j + 1];
        }
#pragma unroll
        for (int mi = 0; mi < 2; mi++) {
#pragma unroll
            for (int nj = 0; nj < 8; nj++) {
                float2 c0 = __half22float2(*reinterpret_cast<__half2*>(&acc[mi][nj][0]));
                float2 c1 = __half22float2(*reinterpret_cast<__half2*>(&acc[mi][nj][1]));
                float bnd[4];
                bnd[0] = fabsf(c0.x) + ti[mi][0] * tj0[nj];
                bnd[1] = fabsf(c0.y) + ti[mi][0] * tj1[nj];
                bnd[2] = fabsf(c1.x) + ti[mi][1] * tj0[nj];
                bnd[3] = fabsf(c1.y) + ti[mi][1] * tj1[nj];
                float bm = fmaxf(fmaxf(bnd[0], bnd[1]), fmaxf(bnd[2], bnd[3]));
                if (__any_sync(0xffffffffu, bm >= SCREEN_T)) {
#pragma unroll
                    for (int r = 0; r < 4; r++) {
                        if (bnd[r] >= SCREEN_T) {
                            int i = ib * TB + m0 + mi * 16 + g + (r >> 1) * 8;
                            int j = jb * TB + n0 + nj * 8 + 2 * tg + (r & 1);
                            if (i < j) {
                                const float4* xi = reinterpret_cast<const float4*>(x) + (size_t)i * 32;
                                const float4* xj = reinterpret_cast<const float4*>(x) + (size_t)j * 32;
                                float cdot = 0.f;
                                for (int f = 0; f < 32; f++) {
                                    float4 a4 = xi[f], b4 = xj[f];
                                    cdot += a4.x * b4.x + a4.y * b4.y + a4.z * b4.z + a4.w * b4.w;
                                }
                                cdot *= g_rnorm[i] * g_rnorm[j];
                                if (cdot * cdot >= 0.9f) {
                                    atomicAdd(&g_deg[i], 1);
                                    atomicAdd(&g_deg[j], 1);
                                    const float* xif = x + (size_t)i * F_DIM;
                                    const float* xjf = x + (size_t)j * F_DIM;
                                    float* ni = g_neigh + (size_t)i * F_DIM;
                                    float* njp = g_neigh + (size_t)j * F_DIM;
                                    for (int f = 0; f < F_DIM; f++) {
                                        atomicAdd(&ni[f], xjf[f]);
                                        atomicAdd(&njp[f], xif[f]);
                                    }
                                }
                            }
                        }
                    }
                }
            }
        }
    }
}

// ---------------- kernel 3: aggregation + MLP (f32x2, 2 threads/row by OUTPUT half) + BN ----------------
__global__ void __launch_bounds__(128) k_mlp(const float* __restrict__ x,
                                             const float* __restrict__ W1, const float* __restrict__ b1,
                                             const float* __restrict__ W2, const float* __restrict__ b2,
                                             const float* __restrict__ W3, const float* __restrict__ b3,
                                             const float* __restrict__ gamma,
                                             const float* __restrict__ beta,
                                             float* __restrict__ out) {
    __shared__ float sW1[F_DIM * H1_DIM];
    __shared__ float sW2[H1_DIM * H2_DIM];
    __shared__ float sW3[H2_DIM * OUT_DIM];
    __shared__ float sb1[H1_DIM], sb2[H2_DIM], sb3[OUT_DIM];
    __shared__ double swarp[4 * 4];
    __shared__ float s_scale[2], s_shift[2];

    int tid = threadIdx.x;
    {   // float4 weight staging
        const float4* W14 = reinterpret_cast<const float4*>(W1);
        float4* sW14 = reinterpret_cast<float4*>(sW1);
        for (int i = tid; i < F_DIM * H1_DIM / 4; i += 128) sW14[i] = W14[i];
        const float4* W24 = reinterpret_cast<const float4*>(W2);
        float4* sW24 = reinterpret_cast<float4*>(sW2);
        for (int i = tid; i < H1_DIM * H2_DIM / 4; i += 128) sW24[i] = W24[i];
    }
    if (tid < H2_DIM * OUT_DIM) sW3[tid] = W3[tid];
    if (tid < H1_DIM) sb1[tid] = b1[tid];
    if (tid < H2_DIM) sb2[tid] = b2[tid];
    if (tid < OUT_DIM) sb3[tid] = b3[tid];
    __syncthreads();

    int p = tid & 1;                       // output half
    int row = blockIdx.x * 64 + (tid >> 1);
    const float4* xr4 = reinterpret_cast<const float4*>(x) + (size_t)row * 32;
    float4* nr4 = reinterpret_cast<float4*>(g_neigh) + (size_t)row * 32;
    int d = g_deg[row];
    float invd = d > 0 ? 1.0f / (float)d : 0.f;

    const unsigned long long* sW1p = reinterpret_cast<const unsigned long long*>(sW1);
    const unsigned long long* sW2p = reinterpret_cast<const unsigned long long*>(sW2);

    // stage 1: h1 half [p*32, p*32+32) as 16 packed f32x2, over all f
    unsigned long long h1p[16];
#pragma unroll
    for (int m = 0; m < 16; m++) PACK2(h1p[m], sb1[p * 32 + 2 * m], sb1[p * 32 + 2 * m + 1]);
#pragma unroll
    for (int c = 0; c < 4; c++) {
        float4 xv[8];
#pragma unroll
        for (int u = 0; u < 8; u++) xv[u] = xr4[c * 8 + u];
        if (d > 0) {
#pragma unroll
            for (int u = 0; u < 8; u++) {
                float4 nv = nr4[c * 8 + u];
                xv[u].x = 0.5f * (xv[u].x + nv.x * invd);
                xv[u].y = 0.5f * (xv[u].y + nv.y * invd);
                xv[u].z = 0.5f * (xv[u].z + nv.z * invd);
                xv[u].w = 0.5f * (xv[u].w + nv.w * invd);
            }
        }
#pragma unroll
        for (int u = 0; u < 8; u++) {
            float av[4] = { xv[u].x, xv[u].y, xv[u].z, xv[u].w };
#pragma unroll
            for (int e = 0; e < 4; e++) {
                int f = c * 32 + u * 4 + e;
                unsigned long long apk;
                PACK2(apk, av[e], av[e]);
                const unsigned long long* wrow = sW1p + f * 32 + p * 16;
#pragma unroll
                for (int m = 0; m < 16; m++) FMA2(h1p[m], apk, wrow[m]);
            }
        }
    }
    if (d > 0 && p == 0) {   // re-zero consumed neighbor rows (once per row)
        float4 z = make_float4(0.f, 0.f, 0.f, 0.f);
#pragma unroll
        for (int u = 0; u < 32; u++) nr4[u] = z;
    }

    // relu (local half) + stage 2: full h2 from own k-half
    unsigned long long h2p[16];
#pragma unroll
    for (int m = 0; m < 16; m++) {
        if (p == 0) PACK2(h2p[m], sb2[2 * m], sb2[2 * m + 1]);
        else        h2p[m] = 0ull;
    }
#pragma unroll
    for (int kl = 0; kl < 32; kl++) {
        int k = p * 32 + kl;
        float lo, hi;
        UNPACK2(lo, hi, h1p[kl >> 1]);
        float hk = fmaxf((kl & 1) ? hi : lo, 0.f);
        unsigned long long hpk;
        PACK2(hpk, hk, hk);
        const unsigned long long* wrow = sW2p + k * 16;
#pragma unroll
        for (int m = 0; m < 16; m++) FMA2(h2p[m], hpk, wrow[m]);
    }

    // single exchange: sum partner's h2 half, fused with relu + stage 3
    float l0 = sb3[0], l1 = sb3[1];
#pragma unroll
    for (int m = 0; m < 16; m++) {
        float lo, hi;
        UNPACK2(lo, hi, h2p[m]);
        lo += __shfl_xor_sync(0xffffffffu, lo, 1);
        hi += __shfl_xor_sync(0xffffffffu, hi, 1);
        lo = fmaxf(lo, 0.f);
        hi = fmaxf(hi, 0.f);
        l0 += lo * sW3[(2 * m) * 2 + 0] + hi * sW3[(2 * m + 1) * 2 + 0];
        l1 += lo * sW3[(2 * m) * 2 + 1] + hi * sW3[(2 * m + 1) * 2 + 1];
    }

    // BN statistics (double) -> 4 atomics per block (only p==0 lanes contribute)
    double v[4];
    if (p == 0) { v[0] = (double)l0; v[1] = (double)l1; v[2] = (double)l0 * l0; v[3] = (double)l1 * l1; }
    else        { v[0] = v[1] = v[2] = v[3] = 0.0; }
    int lane = tid & 31, wid = tid >> 5;
#pragma unroll
    for (int s = 0; s < 4; s++) {
        double t = v[s];
#pragma unroll
        for (int o = 16; o > 0; o >>= 1) t += __shfl_xor_sync(0xffffffffu, t, o);
        if (lane == 0) swarp[wid * 4 + s] = t;
    }
    __syncthreads();
    if (tid < 4) {
        double s = 0.0;
#pragma unroll
        for (int w = 0; w < 4; w++) s += swarp[w * 4 + tid];
        if (tid < 2) atomicAdd(&g_sum[tid], s);
        else         atomicAdd(&g_sq[tid - 2], s);
    }

    // grid-wide arrival: wait until every block has deposited its stats
    if (tid == 0) {
        __threadfence();
        atomicAdd(&g_done, 1);
        while (atomicAdd(&g_done, 0) < MLP_BLOCKS) { }
    }
    __syncthreads();

    if (tid < 2) {
        int c = tid;
        float n = (float)N_ROWS;
        float mu = (float)atomicAdd(&g_sum[c], 0.0) / n;
        float var = (float)atomicAdd(&g_sq[c], 0.0) / n - mu * mu;
        float inv = rsqrtf(var + 1e-5f);
        float gch = gamma[c];
        s_scale[c] = inv * gch;
        s_shift[c] = beta[c] - mu * inv * gch;
    }
    __syncthreads();

    if (p == 0) {
        float2 o;
        o.x = l0 * s_scale[0] + s_shift[0];
        o.y = l1 * s_scale[1] + s_shift[1];
        reinterpret_cast<float2*>(out)[row] = o;
    }
}

// ---------------- launch ----------------
extern "C" void kernel_launch(void* const* d_in, const int* in_sizes, int n_in,
                              void* d_out, int out_size) {
    const float* x     = (const float*)d_in[0];
    const float* W1    = (const float*)d_in[1];
    const float* b1    = (const float*)d_in[2];
    const float* W2    = (const float*)d_in[3];
    const float* b2    = (const float*)d_in[4];
    const float* W3    = (const float*)d_in[5];
    const float* b3    = (const float*)d_in[6];
    const float* gamma = (const float*)d_in[7];
    const float* beta  = (const float*)d_in[8];
    float* out = (float*)d_out;

    k_norm<<<N_ROWS / 32, 256>>>(x);   // 512 blocks, 8 warps x 4 rows each
    k_gram<<<N_TILES, 256>>>(x);
    k_mlp<<<MLP_BLOCKS, 128>>>(x, W1, b1, W2, b2, W3, b3, gamma, beta, out);
}

// round 15
// speedup vs baseline: 1.0483x; 1.0483x over previous
#include <cuda_runtime.h>
#include <cuda_bf16.h>
#include <cuda_fp16.h>
#include <cuda_fp8.h>
#include <cstdint>
#include <math.h>

#define N_ROWS 16384
#define F_DIM  128
#define H1_DIM 64
#define H2_DIM 32
#define OUT_DIM 2

#define TB      128                       // gram tile (square), K=64 head
#define NB      (N_ROWS / TB)             // 128
#define N_TILES (NB * (NB + 1) / 2)       // 8256

#define SCREEN_T 0.9186f                  // sqrt(0.9) - 0.03 margin (fp8 dot + f16 acc noise)
#define TILE_BYTES 8192                   // 128 rows x 64B head
#define MLP_BLOCKS (N_ROWS / 128)         // 128

// ---------------- device scratch (zero-initialized at load) ----------------
__device__ __align__(128) uint32_t g_x8[N_ROWS * 16];  // 1 MB: head rows pre-swizzled per 8KB tile
__device__ __align__(128) float    g_tail[N_ROWS];     // tail norm of normalized row
__device__ float    g_rnorm[N_ROWS];
__device__ float    g_neigh[N_ROWS * F_DIM];           // zero except edge rows (re-zeroed in k_mlp)
__device__ int      g_deg[N_ROWS];
__device__ double   g_sum[2];
__device__ double   g_sq[2];
__device__ int      g_done;

__device__ __forceinline__ uint32_t smem_u32(const void* p) {
    uint32_t a;
    asm("{ .reg .u64 t; cvta.to.shared.u64 t, %1; cvt.u32.u64 %0, t; }" : "=r"(a) : "l"(p));
    return a;
}

// byte offset inside an 8KB tile: two 64B logical rows per 128B smem row, XOR swizzle.
__device__ __forceinline__ uint32_t pack_off(int r, int c) {
    int R = r >> 1;
    int u = ((r & 1) << 2) | c;
    return (uint32_t)(R * 128 + ((u ^ (R & 7)) << 4));
}

// triangular decode: linear tile t -> (ib, jb), jb >= ib
__device__ __forceinline__ void decode_tile(int t, int& ib, int& jb) {
    int u = N_TILES - 1 - t;
    int rb = (int)((sqrtf(8.0f * (float)u + 1.0f) - 1.0f) * 0.5f);
    while (rb * (rb + 1) / 2 > u) rb--;
    while ((rb + 1) * (rb + 2) / 2 <= u) rb++;
    ib = NB - 1 - rb;
    jb = NB - 1 - (u - rb * (rb + 1) / 2);
}

__device__ __forceinline__ void bulk_cp(uint32_t dst, const void* src, uint32_t bytes,
                                        uint32_t mbar) {
    asm volatile(
        "cp.async.bulk.shared::cta.global.mbarrier::complete_tx::bytes [%0], [%1], %2, [%3];"
        :: "r"(dst), "l"(src), "r"(bytes), "r"(mbar) : "memory");
}
__device__ __forceinline__ void mbar_init(uint32_t addr, uint32_t cnt) {
    asm volatile("mbarrier.init.shared.b64 [%0], %1;" :: "r"(addr), "r"(cnt) : "memory");
}
__device__ __forceinline__ void mbar_expect_tx(uint32_t addr, uint32_t tx) {
    asm volatile("mbarrier.arrive.expect_tx.shared.b64 _, [%0], %1;"
                 :: "r"(addr), "r"(tx) : "memory");
}
__device__ __forceinline__ void mbar_wait(uint32_t addr, uint32_t parity) {
    asm volatile(
        "{\n\t.reg .pred P;\n\t"
        "WAITLP_%=:\n\t"
        "mbarrier.try_wait.parity.acquire.cta.shared::cta.b64 P, [%0], %1, 0x989680;\n\t"
        "@P bra.uni WAITDN_%=;\n\t"
        "bra.uni WAITLP_%=;\n\t"
        "WAITDN_%=:\n\t}"
        :: "r"(addr), "r"(parity) : "memory");
}

// packed f32x2 helpers
#define PACK2(out, lo, hi) \
    asm("mov.b64 %0, {%1, %2};" : "=l"(out) : "f"(lo), "f"(hi))
#define UNPACK2(lo, hi, in) \
    asm("mov.b64 {%0, %1}, %2;" : "=f"(lo), "=f"(hi) : "l"(in))
#define FMA2(acc, a, b) \
    asm("fma.rn.f32x2 %0, %1, %2, %0;" : "+l"(acc) : "l"(a), "l"(b))

// ---------------- kernel 1: norms, head->e4m3 (pre-swizzled), tail norms ----------------
// 8 lanes per row, 4 rows per warp: MLP=4 loads, 3-step butterfly reduce.
__global__ void __launch_bounds__(256) k_norm(const float* __restrict__ x) {
    if (blockIdx.x == 0 && threadIdx.x == 0) {
        g_sum[0] = 0.0; g_sum[1] = 0.0; g_sq[0] = 0.0; g_sq[1] = 0.0;
        g_done = 0;
    }
    int warp = (blockIdx.x * blockDim.x + threadIdx.x) >> 5;
    int lane = threadIdx.x & 31;
    int l = lane & 7;                 // lane within row (0..7)
    int row = warp * 4 + (lane >> 3); // 4 rows per warp
    if (row >= N_ROWS) return;

    const float4* xr = reinterpret_cast<const float4*>(x) + (size_t)row * 32;
    float4 v[4];
#pragma unroll
    for (int k = 0; k < 4; k++) v[k] = xr[l + 8 * k];   // k=0,1 head; k=2,3 tail

    float sh = v[0].x * v[0].x + v[0].y * v[0].y + v[0].z * v[0].z + v[0].w * v[0].w
             + v[1].x * v[1].x + v[1].y * v[1].y + v[1].z * v[1].z + v[1].w * v[1].w;
    float st = v[2].x * v[2].x + v[2].y * v[2].y + v[2].z * v[2].z + v[2].w * v[2].w
             + v[3].x * v[3].x + v[3].y * v[3].y + v[3].z * v[3].z + v[3].w * v[3].w;
#pragma unroll
    for (int o = 4; o > 0; o >>= 1) {
        sh += __shfl_xor_sync(0xffffffffu, sh, o);
        st += __shfl_xor_sync(0xffffffffu, st, o);
    }
    float ss = sh + st;
    float inv = 1.0f / (sqrtf(ss) + 1e-12f);

    int t = row >> 7, rl = row & 127;
#pragma unroll
    for (int h = 0; h < 2; h++) {     // head words: j = l and l+8
        __nv_fp8x2_storage_t p0 = __nv_cvt_float2_to_fp8x2(
            make_float2(v[h].x * inv, v[h].y * inv), __NV_SATFINITE, __NV_E4M3);
        __nv_fp8x2_storage_t p1 = __nv_cvt_float2_to_fp8x2(
            make_float2(v[h].z * inv, v[h].w * inv), __NV_SATFINITE, __NV_E4M3);
        uint32_t word = (uint32_t)p0 | ((uint32_t)p1 << 16);
        int j = l + 8 * h;
        g_x8[t * 2048 + (pack_off(rl, j >> 2) >> 2) + (j & 3)] = word;
    }
    if (l == 0) {
        g_tail[row] = sqrtf(st) * inv;
        g_rnorm[row] = inv;
        g_deg[row] = 0;
    }
}

// ---------------- kernel 2: fp8 head-gram (f16 acc, occ=3) + cheap screen + exact recheck ----------------
__global__ void __launch_bounds__(256, 3) k_gram(const float* __restrict__ x) {
    int ib, jb;
    decode_tile(blockIdx.x, ib, jb);
    bool diag = (ib == jb);

    __shared__ alignas(1024) char sA[TILE_BYTES];
    __shared__ alignas(1024) char sB[TILE_BYTES];
    __shared__ alignas(16) float stA[TB];
    __shared__ alignas(16) float stB[TB];
    __shared__ alignas(8) unsigned long long mbar_s;

    int tid = threadIdx.x;
    uint32_t sa = smem_u32(sA), sbm = smem_u32(sB);
    uint32_t mbar = smem_u32(&mbar_s);

    if (tid == 0) mbar_init(mbar, 1);
    __syncthreads();
    if (tid == 0) {
        uint32_t tx = diag ? (TILE_BYTES + 512) : (2 * TILE_BYTES + 1024);
        mbar_expect_tx(mbar, tx);
        bulk_cp(sa, g_x8 + (size_t)ib * 2048, TILE_BYTES, mbar);
        bulk_cp(smem_u32(stA), g_tail + ib * TB, 512, mbar);
        if (!diag) {
            bulk_cp(sbm, g_x8 + (size_t)jb * 2048, TILE_BYTES, mbar);
            bulk_cp(smem_u32(stB), g_tail + jb * TB, 512, mbar);
        }
    }
    mbar_wait(mbar, 0);

    uint32_t sb_use = diag ? sa : sbm;

    int wid = tid >> 5, lane = tid & 31;
    int m0 = (wid & 3) * 32;   // 4 warps along M
    int n0 = (wid >> 2) * 64;  // 2 warps along N

    // f16 accumulators
    uint32_t acc[2][8][2];
#pragma unroll
    for (int mi = 0; mi < 2; mi++)
#pragma unroll
        for (int nj = 0; nj < 8; nj++) {
            acc[mi][nj][0] = 0u; acc[mi][nj][1] = 0u;
        }

    int q = lane >> 3, L = lane & 7;
    int rq = (q & 1) * 8 + L;
    int kq = q >> 1;

#pragma unroll
    for (int kk = 0; kk < 2; kk++) {           // 2 chunks of k=32 fp8 (head only)
        int cbase = kk * 2 + kq;
        uint32_t a[2][4];
#pragma unroll
        for (int mi = 0; mi < 2; mi++) {
            uint32_t addr = sa + pack_off(m0 + mi * 16 + rq, cbase);
            asm volatile("ldmatrix.sync.aligned.m8n8.x4.shared.b16 {%0,%1,%2,%3}, [%4];"
                         : "=r"(a[mi][0]), "=r"(a[mi][1]), "=r"(a[mi][2]), "=r"(a[mi][3])
                         : "r"(addr));
        }
        uint32_t b[8][2];
#pragma unroll
        for (int nq4 = 0; nq4 < 4; nq4++) {
            uint32_t r0, r1, r2, r3;
            uint32_t addr = sb_use + pack_off(n0 + nq4 * 16 + rq, cbase);
            asm volatile("ldmatrix.sync.aligned.m8n8.x4.shared.b16 {%0,%1,%2,%3}, [%4];"
                         : "=r"(r0), "=r"(r1), "=r"(r2), "=r"(r3)
                         : "r"(addr));
            b[nq4 * 2 + 0][0] = r0; b[nq4 * 2 + 0][1] = r2;
            b[nq4 * 2 + 1][0] = r1; b[nq4 * 2 + 1][1] = r3;
        }
#pragma unroll
        for (int mi = 0; mi < 2; mi++)
#pragma unroll
            for (int nj = 0; nj < 8; nj++)
                asm volatile(
                    "mma.sync.aligned.m16n8k32.row.col.f16.e4m3.e4m3.f16 "
                    "{%0,%1}, {%2,%3,%4,%5}, {%6,%7}, {%0,%1};"
                    : "+r"(acc[mi][nj][0]), "+r"(acc[mi][nj][1])
                    : "r"(a[mi][0]), "r"(a[mi][1]), "r"(a[mi][2]), "r"(a[mi][3]),
                      "r"(b[nj][0]), "r"(b[nj][1]));
    }

    // ---- epilogue: minimal coarse screen (amax + warp-max tail bound) ----
    int g = lane >> 2, tg = lane & 3;
    const float* stB_use = diag ? stA : stB;

    __half2 hmax = __float2half2_rn(0.f);
#pragma unroll
    for (int mi = 0; mi < 2; mi++)
#pragma unroll
        for (int nj = 0; nj < 8; nj++)
#pragma unroll
            for (int r2 = 0; r2 < 2; r2++)
                hmax = __hmax2(hmax, __habs2(*reinterpret_cast<__half2*>(&acc[mi][nj][r2])));
    float amax = fmaxf(__low2float(hmax), __high2float(hmax));

    float timax = fmaxf(fmaxf(stA[m0 + g], stA[m0 + g + 8]),
                        fmaxf(stA[m0 + 16 + g], stA[m0 + 16 + g + 8]));
    float tjmax = fmaxf(stB_use[n0 + lane], stB_use[n0 + 32 + lane]);
#pragma unroll
    for (int o = 16; o > 0; o >>= 1)
        tjmax = fmaxf(tjmax, __shfl_xor_sync(0xffffffffu, tjmax, o));

    if (__any_sync(0xffffffffu, amax + timax * tjmax >= SCREEN_T)) {
        float ti[2][2];
#pragma unroll
        for (int mi = 0; mi < 2; mi++)
#pragma unroll
            for (int h = 0; h < 2; h++)
                ti[mi][h] = stA[m0 + mi * 16 + g + h * 8];
        float tj0[8], tj1[8];
#pragma unroll
        for (int nj = 0; nj < 8; nj++) {
            int j = n0 + nj * 8 + 2 * tg;
            tj0[nj] = stB_use[j];
            tj1[nj] = stB_use[j + 1];
        }
#pragma unroll
        for (int mi = 0; mi < 2; mi++) {
#pragma unroll
            for (int nj = 0; nj < 8; nj++) {
                float2 c0 = __half22float2(*reinterpret_cast<__half2*>(&acc[mi][nj][0]));
                float2 c1 = __half22float2(*reinterpret_cast<__half2*>(&acc[mi][nj][1]));
                float bnd[4];
                bnd[0] = fabsf(c0.x) + ti[mi][0] * tj0[nj];
                bnd[1] = fabsf(c0.y) + ti[mi][0] * tj1[nj];
                bnd[2] = fabsf(c1.x) + ti[mi][1] * tj0[nj];
                bnd[3] = fabsf(c1.y) + ti[mi][1] * tj1[nj];
                float bm = fmaxf(fmaxf(bnd[0], bnd[1]), fmaxf(bnd[2], bnd[3]));
                if (__any_sync(0xffffffffu, bm >= SCREEN_T)) {
#pragma unroll
                    for (int r = 0; r < 4; r++) {
                        if (bnd[r] >= SCREEN_T) {
                            int i = ib * TB + m0 + mi * 16 + g + (r >> 1) * 8;
                            int j = jb * TB + n0 + nj * 8 + 2 * tg + (r & 1);
                            if (i < j) {
                                const float4* xi = reinterpret_cast<const float4*>(x) + (size_t)i * 32;
                                const float4* xj = reinterpret_cast<const float4*>(x) + (size_t)j * 32;
                                float cdot = 0.f;
                                for (int f = 0; f < 32; f++) {
                                    float4 a4 = xi[f], b4 = xj[f];
                                    cdot += a4.x * b4.x + a4.y * b4.y + a4.z * b4.z + a4.w * b4.w;
                                }
                                cdot *= g_rnorm[i] * g_rnorm[j];
                                if (cdot * cdot >= 0.9f) {
                                    atomicAdd(&g_deg[i], 1);
                                    atomicAdd(&g_deg[j], 1);
                                    const float* xif = x + (size_t)i * F_DIM;
                                    const float* xjf = x + (size_t)j * F_DIM;
                                    float* ni = g_neigh + (size_t)i * F_DIM;
                                    float* njp = g_neigh + (size_t)j * F_DIM;
                                    for (int f = 0; f < F_DIM; f++) {
                                        atomicAdd(&ni[f], xjf[f]);
                                        atomicAdd(&njp[f], xif[f]);
                                    }
                                }
                            }
                        }
                    }
                }
            }
        }
    }
}

// ---------------- kernel 3: aggregation + MLP (f32x2, batched loads) + BN (fused) ----------------
__global__ void __launch_bounds__(128) k_mlp(const float* __restrict__ x,
                                             const float* __restrict__ W1, const float* __restrict__ b1,
                                             const float* __restrict__ W2, const float* __restrict__ b2,
                                             const float* __restrict__ W3, const float* __restrict__ b3,
                                             const float* __restrict__ gamma,
                                             const float* __restrict__ beta,
                                             float* __restrict__ out) {
    __shared__ float sW1[F_DIM * H1_DIM];
    __shared__ float sW2[H1_DIM * H2_DIM];
    __shared__ float sW3[H2_DIM * OUT_DIM];
    __shared__ float sb1[H1_DIM], sb2[H2_DIM], sb3[OUT_DIM];
    __shared__ double swarp[4 * 4];
    __shared__ float s_scale[2], s_shift[2];

    int tid = threadIdx.x;
    {   // float4 weight staging
        const float4* W14 = reinterpret_cast<const float4*>(W1);
        float4* sW14 = reinterpret_cast<float4*>(sW1);
        for (int i = tid; i < F_DIM * H1_DIM / 4; i += 128) sW14[i] = W14[i];
        const float4* W24 = reinterpret_cast<const float4*>(W2);
        float4* sW24 = reinterpret_cast<float4*>(sW2);
        for (int i = tid; i < H1_DIM * H2_DIM / 4; i += 128) sW24[i] = W24[i];
    }
    if (tid < H2_DIM * OUT_DIM) sW3[tid] = W3[tid];
    if (tid < H1_DIM) sb1[tid] = b1[tid];
    if (tid < H2_DIM) sb2[tid] = b2[tid];
    if (tid < OUT_DIM) sb3[tid] = b3[tid];
    __syncthreads();

    int row = blockIdx.x * 128 + tid;
    const float4* xr4 = reinterpret_cast<const float4*>(x) + (size_t)row * 32;
    float4* nr4 = reinterpret_cast<float4*>(g_neigh) + (size_t)row * 32;
    int d = g_deg[row];
    float invd = d > 0 ? 1.0f / (float)d : 0.f;

    const unsigned long long* sW1p = reinterpret_cast<const unsigned long long*>(sW1);
    const unsigned long long* sW2p = reinterpret_cast<const unsigned long long*>(sW2);

    // stage 1: h1 (32 packed f32x2); x loaded in 4 batches of 8 float4 (MLP=8)
    unsigned long long h1p[32];
#pragma unroll
    for (int m = 0; m < 32; m++) PACK2(h1p[m], sb1[2 * m], sb1[2 * m + 1]);
#pragma unroll
    for (int c = 0; c < 4; c++) {
        float4 xv[8];
#pragma unroll
        for (int u = 0; u < 8; u++) xv[u] = xr4[c * 8 + u];
        if (d > 0) {
#pragma unroll
            for (int u = 0; u < 8; u++) {
                float4 nv = nr4[c * 8 + u];
                xv[u].x = 0.5f * (xv[u].x + nv.x * invd);
                xv[u].y = 0.5f * (xv[u].y + nv.y * invd);
                xv[u].z = 0.5f * (xv[u].z + nv.z * invd);
                xv[u].w = 0.5f * (xv[u].w + nv.w * invd);
            }
        }
#pragma unroll
        for (int u = 0; u < 8; u++) {
            float av[4] = { xv[u].x, xv[u].y, xv[u].z, xv[u].w };
#pragma unroll
            for (int e = 0; e < 4; e++) {
                int f = c * 32 + u * 4 + e;
                unsigned long long apk;
                PACK2(apk, av[e], av[e]);
                const unsigned long long* wrow = sW1p + f * 32;
#pragma unroll
                for (int m = 0; m < 32; m++) FMA2(h1p[m], apk, wrow[m]);
            }
        }
    }
    if (d > 0) {   // re-zero consumed neighbor rows so graph replays stay correct
        float4 z = make_float4(0.f, 0.f, 0.f, 0.f);
#pragma unroll
        for (int u = 0; u < 32; u++) nr4[u] = z;
    }

    // relu + stage 2: h2 (16 packed f32x2)
    unsigned long long h2p[16];
#pragma unroll
    for (int m = 0; m < 16; m++) PACK2(h2p[m], sb2[2 * m], sb2[2 * m + 1]);
#pragma unroll
    for (int k = 0; k < H1_DIM; k++) {
        float lo, hi;
        UNPACK2(lo, hi, h1p[k >> 1]);
        float hk = fmaxf((k & 1) ? hi : lo, 0.f);
        unsigned long long hpk;
        PACK2(hpk, hk, hk);
        const unsigned long long* wrow = sW2p + k * 16;
#pragma unroll
        for (int m = 0; m < 16; m++) FMA2(h2p[m], hpk, wrow[m]);
    }

    // relu + stage 3
    float l0 = sb3[0], l1 = sb3[1];
#pragma unroll
    for (int m = 0; m < 16; m++) {
        float lo, hi;
        UNPACK2(lo, hi, h2p[m]);
        lo = fmaxf(lo, 0.f);
        hi = fmaxf(hi, 0.f);
        l0 += lo * sW3[(2 * m) * 2 + 0] + hi * sW3[(2 * m + 1) * 2 + 0];
        l1 += lo * sW3[(2 * m) * 2 + 1] + hi * sW3[(2 * m + 1) * 2 + 1];
    }

    // BN statistics (double) -> 4 atomics per block
    double v[4] = { (double)l0, (double)l1, (double)l0 * l0, (double)l1 * l1 };
    int lane = tid & 31, wid = tid >> 5;
#pragma unroll
    for (int s = 0; s < 4; s++) {
        double t = v[s];
#pragma unroll
        for (int o = 16; o > 0; o >>= 1) t += __shfl_xor_sync(0xffffffffu, t, o);
        if (lane == 0) swarp[wid * 4 + s] = t;
    }
    __syncthreads();
    if (tid < 4) {
        double s = 0.0;
#pragma unroll
        for (int w = 0; w < 4; w++) s += swarp[w * 4 + tid];
        if (tid < 2) atomicAdd(&g_sum[tid], s);
        else         atomicAdd(&g_sq[tid - 2], s);
    }

    // grid-wide arrival: wait until every block has deposited its stats
    if (tid == 0) {
        __threadfence();
        atomicAdd(&g_done, 1);
        while (atomicAdd(&g_done, 0) < MLP_BLOCKS) { }
    }
    __syncthreads();

    if (tid < 2) {
        int c = tid;
        float n = (float)N_ROWS;
        float mu = (float)atomicAdd(&g_sum[c], 0.0) / n;
        float var = (float)atomicAdd(&g_sq[c], 0.0) / n - mu * mu;
        float inv = rsqrtf(var + 1e-5f);
        float gch = gamma[c];
        s_scale[c] = inv * gch;
        s_shift[c] = beta[c] - mu * inv * gch;
    }
    __syncthreads();

    float2 o;
    o.x = l0 * s_scale[0] + s_shift[0];
    o.y = l1 * s_scale[1] + s_shift[1];
    reinterpret_cast<float2*>(out)[row] = o;
}

// ---------------- launch ----------------
extern "C" void kernel_launch(void* const* d_in, const int* in_sizes, int n_in,
                              void* d_out, int out_size) {
    const float* x     = (const float*)d_in[0];
    const float* W1    = (const float*)d_in[1];
    const float* b1    = (const float*)d_in[2];
    const float* W2    = (const float*)d_in[3];
    const float* b2    = (const float*)d_in[4];
    const float* W3    = (const float*)d_in[5];
    const float* b3    = (const float*)d_in[6];
    const float* gamma = (const float*)d_in[7];
    const float* beta  = (const float*)d_in[8];
    float* out = (float*)d_out;

    k_norm<<<N_ROWS / 32, 256>>>(x);   // 512 blocks, 8 warps x 4 rows each
    k_gram<<<N_TILES, 256>>>(x);
    k_mlp<<<MLP_BLOCKS, 128>>>(x, W1, b1, W2, b2, W3, b3, gamma, beta, out);
}